// round 5
// baseline (speedup 1.0000x reference)
#include <cuda_runtime.h>
#include <math.h>
#include <stdint.h>

#define BB   8
#define NN   2048
#define NP   (BB*NN)      /* 16384 points total */
#define KNN  20
#define DMAX 256

// ---------------- device scratch (no allocations allowed) ----------------
__device__ float g_bufA[(size_t)NP * DMAX];
__device__ float g_bufB[(size_t)NP * DMAX];
__device__ float g_xx[NP];
__device__ float g_dist[(size_t)BB * NN * NN];      // 134 MB
__device__ int   g_idx[(size_t)NP * KNN];
__device__ float g_U[(size_t)NP * DMAX];
__device__ float g_V[(size_t)NP * DMAX];
__device__ float g_maxh[(size_t)NP * DMAX];
__device__ float g_minh[(size_t)NP * DMAX];
__device__ float g_weff[DMAX * 128];                // (Wc - Wn), D x C (C <= 128)
__device__ float g_stats[2 * DMAX];                 // [0..255]=sum, [256..511]=sumsq
__device__ float g_scale[DMAX];
__device__ float g_shift[DMAX];
__device__ float g_gmax[BB * DMAX];

// ---------------- squared norms ----------------
__global__ void xx_kernel(const float* __restrict__ x, float* __restrict__ xx, int C) {
    int p = blockIdx.x * blockDim.x + threadIdx.x;
    if (p >= NP) return;
    const float* xr = x + (size_t)p * C;
    float s = 0.f;
    for (int c = 0; c < C; c++) s = fmaf(xr[c], xr[c], s);
    xx[p] = s;
}

// ---------------- generic tiled NT GEMM: out[i,j] = dot(A[i,:], B[j,:]) ----------------
// epi==0: out = acc + (bias ? bias[j] : 0)
// epi==1: out = 2*acc - xxA[i] - xxB[j]   (neg squared distance for kNN)
__global__ __launch_bounds__(256)
void gemm_nt_kernel(const float* __restrict__ A, int lda, size_t strideA,
                    const float* __restrict__ Bm, int ldb, size_t strideB,
                    float* __restrict__ Cm, int ldc, size_t strideC,
                    int M, int Ncols, int Kd,
                    int epi, const float* __restrict__ bias,
                    const float* __restrict__ xxA, const float* __restrict__ xxB,
                    int xxStride)
{
    __shared__ float As[16][68];
    __shared__ float Bs[16][68];
    const int bx = blockIdx.x, by = blockIdx.y, bz = blockIdx.z;
    const float* Ab = A  + (size_t)bz * strideA;
    const float* Bb = Bm + (size_t)bz * strideB;
    float*       Cb = Cm + (size_t)bz * strideC;
    const int tx = threadIdx.x, ty = threadIdx.y;
    const int tid = ty * 16 + tx;
    const int row0 = by * 64, col0 = bx * 64;

    float acc[4][4];
#pragma unroll
    for (int i = 0; i < 4; i++)
#pragma unroll
        for (int j = 0; j < 4; j++) acc[i][j] = 0.f;

    for (int k0 = 0; k0 < Kd; k0 += 16) {
#pragma unroll
        for (int l = 0; l < 4; l++) {
            int e  = tid + l * 256;   // 0..1023
            int r  = e >> 4;
            int kk = e & 15;
            float va = 0.f, vb = 0.f;
            if (k0 + kk < Kd) {
                va = Ab[(size_t)(row0 + r) * lda + k0 + kk];
                vb = Bb[(size_t)(col0 + r) * ldb + k0 + kk];
            }
            As[kk][r] = va;
            Bs[kk][r] = vb;
        }
        __syncthreads();
#pragma unroll
        for (int kk = 0; kk < 16; kk++) {
            float a[4], b[4];
#pragma unroll
            for (int i = 0; i < 4; i++) a[i] = As[kk][ty * 4 + i];
#pragma unroll
            for (int j = 0; j < 4; j++) b[j] = Bs[kk][tx * 4 + j];
#pragma unroll
            for (int i = 0; i < 4; i++)
#pragma unroll
                for (int j = 0; j < 4; j++) acc[i][j] = fmaf(a[i], b[j], acc[i][j]);
        }
        __syncthreads();
    }

#pragma unroll
    for (int i = 0; i < 4; i++) {
        int r = row0 + ty * 4 + i;
#pragma unroll
        for (int j = 0; j < 4; j++) {
            int c = col0 + tx * 4 + j;
            float v;
            if (epi == 0) {
                v = acc[i][j] + (bias ? bias[c] : 0.f);
            } else {
                v = 2.f * acc[i][j] - xxA[(size_t)bz * xxStride + r]
                                    - xxB[(size_t)bz * xxStride + c];
            }
            Cb[(size_t)r * ldc + c] = v;
        }
    }
}

// ---------------- top-k (k=20) per row via iterative argmax ----------------
__global__ __launch_bounds__(256)
void topk_kernel(const float* __restrict__ dist, int* __restrict__ idx)
{
    __shared__ float vals[NN];
    __shared__ float rv[256];
    __shared__ int   ri[256];
    const int row = blockIdx.x;
    const int t = threadIdx.x;
    const float* dr = dist + (size_t)row * NN;
#pragma unroll
    for (int j = t; j < NN; j += 256) vals[j] = dr[j];
    __syncthreads();

    for (int kk = 0; kk < KNN; kk++) {
        float bv = -3.4e38f; int bi = NN;
        for (int j = t; j < NN; j += 256) {
            float v = vals[j];
            if (v > bv) { bv = v; bi = j; }     // strict >: keeps smallest index on tie
        }
        rv[t] = bv; ri[t] = bi;
        __syncthreads();
        for (int s = 128; s >= 32; s >>= 1) {
            if (t < s) {
                float v2 = rv[t + s]; int i2 = ri[t + s];
                if (v2 > rv[t] || (v2 == rv[t] && i2 < ri[t])) { rv[t] = v2; ri[t] = i2; }
            }
            __syncthreads();
        }
        if (t < 32) {
            float v = rv[t]; int bi2 = ri[t];
#pragma unroll
            for (int s = 16; s > 0; s >>= 1) {
                float v2 = __shfl_down_sync(0xffffffffu, v, s);
                int   i2 = __shfl_down_sync(0xffffffffu, bi2, s);
                if (v2 > v || (v2 == v && i2 < bi2)) { v = v2; bi2 = i2; }
            }
            if (t == 0) { idx[(size_t)row * KNN + kk] = bi2; vals[bi2] = -3.4e38f; }
        }
        __syncthreads();
    }
}

// ---------------- weight prep: Weff = Wc - Wn ----------------
__global__ void prep_weff_kernel(const float* __restrict__ w, float* __restrict__ weff,
                                 int C, int D) {
    int i = blockIdx.x * blockDim.x + threadIdx.x;
    if (i >= C * D) return;
    int d = i / C, c = i % C;
    weff[i] = w[(size_t)d * 2 * C + c] - w[(size_t)d * 2 * C + C + c];
}

// ---------------- zero small buffers ----------------
__global__ void zero_kernel(float* __restrict__ a, int n) {
    int i = blockIdx.x * blockDim.x + threadIdx.x;
    if (i < n) a[i] = 0.f;
}

// ---------------- gather h=U+V[idx]; per-(p,d) max/min over k; channel stats ----------------
__global__ void gather_kernel(const float* __restrict__ U, const float* __restrict__ V,
                              const int* __restrict__ idx,
                              float* __restrict__ maxh, float* __restrict__ minh,
                              float* __restrict__ stats, int D)
{
    const int p = blockIdx.x;
    const int d = threadIdx.x;
    __shared__ int sj[KNN];
    if (d < KNN) sj[d] = idx[(size_t)p * KNN + d];
    __syncthreads();
    const int b = p >> 11;                  // p / 2048
    const float* Vb = V + ((size_t)(b << 11)) * D;
    const float u = U[(size_t)p * D + d];
    float mx = -3.4e38f, mn = 3.4e38f, s = 0.f, s2 = 0.f;
#pragma unroll
    for (int kk = 0; kk < KNN; kk++) {
        float h = u + Vb[(size_t)sj[kk] * D + d];
        mx = fmaxf(mx, h); mn = fminf(mn, h);
        s += h; s2 = fmaf(h, h, s2);
    }
    maxh[(size_t)p * D + d] = mx;
    minh[(size_t)p * D + d] = mn;
    atomicAdd(&stats[d], s);
    atomicAdd(&stats[DMAX + d], s2);
}

// ---------------- BN finalize: per-channel scale/shift ----------------
__global__ void finalize_kernel(const float* __restrict__ stats,
                                const float* __restrict__ g, const float* __restrict__ be,
                                float* __restrict__ scale, float* __restrict__ shift,
                                float invcnt)
{
    int d = threadIdx.x;
    float mean = stats[d] * invcnt;
    float var  = stats[DMAX + d] * invcnt - mean * mean;
    float sc   = g[d] * rsqrtf(var + 1e-5f);
    scale[d] = sc;
    shift[d] = be[d] - mean * sc;
}

// ---------------- apply BN + ReLU + (already-max-pooled over k) ----------------
__global__ void apply_kernel(const float* __restrict__ maxh, const float* __restrict__ minh,
                             const float* __restrict__ scale, const float* __restrict__ shift,
                             float* __restrict__ out)
{
    size_t i = (size_t)blockIdx.x * blockDim.x + threadIdx.x;
    int d = threadIdx.x;
    float sc = scale[d];
    float h = (sc >= 0.f) ? maxh[i] : minh[i];
    out[i] = fmaxf(fmaf(h, sc, shift[d]), 0.f);
}

// ---------------- global max over N (values >= 0 after ReLU) ----------------
__global__ void gmax_kernel(const float* __restrict__ x3, float* __restrict__ gmax)
{
    const int b = blockIdx.x >> 6;        // 64 blocks per batch
    const int chunk = blockIdx.x & 63;
    const int d = threadIdx.x;            // 256
    float m = 0.f;
    const int n0 = chunk * 32;
#pragma unroll 4
    for (int n = n0; n < n0 + 32; n++)
        m = fmaxf(m, x3[((size_t)(b * NN + n)) * 256 + d]);
    atomicMax((int*)&gmax[b * 256 + d], __float_as_int(m));  // valid: m >= 0
}

// ---------------- final linear: out = gmax @ wo^T + bo ----------------
__global__ void final_linear_kernel(const float* __restrict__ gmax,
                                    const float* __restrict__ wo, const float* __restrict__ bo,
                                    float* __restrict__ out)
{
    const int b = blockIdx.x;
    const int o = threadIdx.x;            // 256
    __shared__ float h[256];
    h[o] = gmax[b * 256 + o];
    __syncthreads();
    float s = bo[o];
    const float* wr = wo + (size_t)o * 256;
#pragma unroll 8
    for (int c = 0; c < 256; c++) s = fmaf(h[c], wr[c], s);
    out[b * 256 + o] = s;
}

// ============================ host orchestration ============================
extern "C" void kernel_launch(void* const* d_in, const int* in_sizes, int n_in,
                              void* d_out, int out_size)
{
    (void)in_sizes; (void)n_in; (void)out_size;
    const float* x  = (const float*)d_in[0];
    const float* W [3] = {(const float*)d_in[1], (const float*)d_in[5],  (const float*)d_in[9]};
    const float* Bi[3] = {(const float*)d_in[2], (const float*)d_in[6],  (const float*)d_in[10]};
    const float* Ga[3] = {(const float*)d_in[3], (const float*)d_in[7],  (const float*)d_in[11]};
    const float* Be[3] = {(const float*)d_in[4], (const float*)d_in[8],  (const float*)d_in[12]};
    const float* wo = (const float*)d_in[13];
    const float* bo = (const float*)d_in[14];
    float* out = (float*)d_out;

    float *bufA, *bufB, *xx, *dist, *U, *V, *maxh, *minh, *weff, *stats, *scale, *shift, *gmax;
    int* idxp;
    cudaGetSymbolAddress((void**)&bufA,  g_bufA);
    cudaGetSymbolAddress((void**)&bufB,  g_bufB);
    cudaGetSymbolAddress((void**)&xx,    g_xx);
    cudaGetSymbolAddress((void**)&dist,  g_dist);
    cudaGetSymbolAddress((void**)&idxp,  g_idx);
    cudaGetSymbolAddress((void**)&U,     g_U);
    cudaGetSymbolAddress((void**)&V,     g_V);
    cudaGetSymbolAddress((void**)&maxh,  g_maxh);
    cudaGetSymbolAddress((void**)&minh,  g_minh);
    cudaGetSymbolAddress((void**)&weff,  g_weff);
    cudaGetSymbolAddress((void**)&stats, g_stats);
    cudaGetSymbolAddress((void**)&scale, g_scale);
    cudaGetSymbolAddress((void**)&shift, g_shift);
    cudaGetSymbolAddress((void**)&gmax,  g_gmax);

    const int Cs[3] = {3, 64, 128};
    const int Ds[3] = {64, 128, 256};
    const float* xin = x;
    float* outs[3] = {bufA, bufB, bufA};
    const dim3 blk(16, 16);

    for (int l = 0; l < 3; l++) {
        const int C = Cs[l], D = Ds[l];

        // squared norms
        xx_kernel<<<(NP + 255) / 256, 256>>>(xin, xx, C);

        // pairwise neg squared distances per batch: dist[b,i,j] = 2<xi,xj> - |xi|^2 - |xj|^2
        dim3 gd(NN / 64, NN / 64, BB);
        gemm_nt_kernel<<<gd, blk>>>(xin, C, (size_t)NN * C,
                                    xin, C, (size_t)NN * C,
                                    dist, NN, (size_t)NN * NN,
                                    NN, NN, C,
                                    1, nullptr, xx, xx, NN);

        // top-20 neighbor indices per point
        topk_kernel<<<NP, 256>>>(dist, idxp);

        // Weff = Wc - Wn
        prep_weff_kernel<<<(C * D + 255) / 256, 256>>>(W[l], weff, C, D);

        // U = X @ Weff^T + b ;  V = X @ Wn^T
        dim3 gu(D / 64, NP / 64, 1);
        gemm_nt_kernel<<<gu, blk>>>(xin, C, 0, weff, C, 0, U, D, 0,
                                    NP, D, C, 0, Bi[l], nullptr, nullptr, 0);
        gemm_nt_kernel<<<gu, blk>>>(xin, C, 0, W[l] + C, 2 * C, 0, V, D, 0,
                                    NP, D, C, 0, nullptr, nullptr, nullptr, 0);

        // stats reset, gather + per-point max/min + channel sums
        zero_kernel<<<2, 256>>>(stats, 2 * DMAX);
        gather_kernel<<<NP, D>>>(U, V, idxp, maxh, minh, stats, D);

        // BN scale/shift, then apply BN+ReLU to the k-pooled extremum
        finalize_kernel<<<1, D>>>(stats, Ga[l], Be[l], scale, shift,
                                  1.f / (float)((size_t)NP * KNN));
        apply_kernel<<<NP, D>>>(maxh, minh, scale, shift, outs[l]);

        xin = outs[l];
    }

    // global max over N, then final linear
    zero_kernel<<<8, 256>>>(gmax, BB * DMAX);
    gmax_kernel<<<BB * 64, 256>>>(xin, gmax);
    final_linear_kernel<<<BB, 256>>>(gmax, wo, bo, out);
}

// round 6
// speedup vs baseline: 1.0020x; 1.0020x over previous
#include <cuda_runtime.h>
#include <math.h>
#include <stdint.h>

#define BB   8
#define NN   2048
#define NP   (BB*NN)      /* 16384 points total */
#define KNN  20
#define DMAX 256

// ---------------- device scratch (no allocations allowed) ----------------
__device__ float g_bufA[(size_t)NP * DMAX];
__device__ float g_bufB[(size_t)NP * DMAX];
__device__ float g_xx[NP];
__device__ float g_dist[(size_t)BB * NN * NN];      // 134 MB
__device__ int   g_idx[(size_t)NP * KNN];
__device__ float g_U[(size_t)NP * DMAX];
__device__ float g_V[(size_t)NP * DMAX];
__device__ float g_maxh[(size_t)NP * DMAX];
__device__ float g_minh[(size_t)NP * DMAX];
__device__ float g_weff[DMAX * 128];                // (Wc - Wn), D x C (C <= 128)
__device__ float g_stats[2 * DMAX];                 // [0..255]=sum, [256..511]=sumsq
__device__ float g_scale[DMAX];
__device__ float g_shift[DMAX];
__device__ float g_gmax[BB * DMAX];

// ---------------- squared norms ----------------
__global__ void xx_kernel(const float* __restrict__ x, float* __restrict__ xx, int C) {
    int p = blockIdx.x * blockDim.x + threadIdx.x;
    if (p >= NP) return;
    const float* xr = x + (size_t)p * C;
    float s = 0.f;
    for (int c = 0; c < C; c++) s = fmaf(xr[c], xr[c], s);
    xx[p] = s;
}

// ---------------- generic tiled NT GEMM: out[i,j] = dot(A[i,:], B[j,:]) ----------------
// epi==0: out = acc + (bias ? bias[j] : 0)
// epi==1: out = 2*acc - xxA[i] - xxB[j]   (neg squared distance for kNN)
__global__ __launch_bounds__(256)
void gemm_nt_kernel(const float* __restrict__ A, int lda, size_t strideA,
                    const float* __restrict__ Bm, int ldb, size_t strideB,
                    float* __restrict__ Cm, int ldc, size_t strideC,
                    int M, int Ncols, int Kd,
                    int epi, const float* __restrict__ bias,
                    const float* __restrict__ xxA, const float* __restrict__ xxB,
                    int xxStride)
{
    __shared__ float As[16][68];
    __shared__ float Bs[16][68];
    const int bx = blockIdx.x, by = blockIdx.y, bz = blockIdx.z;
    const float* Ab = A  + (size_t)bz * strideA;
    const float* Bb = Bm + (size_t)bz * strideB;
    float*       Cb = Cm + (size_t)bz * strideC;
    const int tx = threadIdx.x, ty = threadIdx.y;
    const int tid = ty * 16 + tx;
    const int row0 = by * 64, col0 = bx * 64;

    float acc[4][4];
#pragma unroll
    for (int i = 0; i < 4; i++)
#pragma unroll
        for (int j = 0; j < 4; j++) acc[i][j] = 0.f;

    for (int k0 = 0; k0 < Kd; k0 += 16) {
#pragma unroll
        for (int l = 0; l < 4; l++) {
            int e  = tid + l * 256;   // 0..1023
            int r  = e >> 4;
            int kk = e & 15;
            float va = 0.f, vb = 0.f;
            if (k0 + kk < Kd) {
                va = Ab[(size_t)(row0 + r) * lda + k0 + kk];
                vb = Bb[(size_t)(col0 + r) * ldb + k0 + kk];
            }
            As[kk][r] = va;
            Bs[kk][r] = vb;
        }
        __syncthreads();
#pragma unroll
        for (int kk = 0; kk < 16; kk++) {
            float a[4], b[4];
#pragma unroll
            for (int i = 0; i < 4; i++) a[i] = As[kk][ty * 4 + i];
#pragma unroll
            for (int j = 0; j < 4; j++) b[j] = Bs[kk][tx * 4 + j];
#pragma unroll
            for (int i = 0; i < 4; i++)
#pragma unroll
                for (int j = 0; j < 4; j++) acc[i][j] = fmaf(a[i], b[j], acc[i][j]);
        }
        __syncthreads();
    }

#pragma unroll
    for (int i = 0; i < 4; i++) {
        int r = row0 + ty * 4 + i;
#pragma unroll
        for (int j = 0; j < 4; j++) {
            int c = col0 + tx * 4 + j;
            float v;
            if (epi == 0) {
                v = acc[i][j] + (bias ? bias[c] : 0.f);
            } else {
                v = 2.f * acc[i][j] - xxA[(size_t)bz * xxStride + r]
                                    - xxB[(size_t)bz * xxStride + c];
            }
            Cb[(size_t)r * ldc + c] = v;
        }
    }
}

// ---------------- top-k (k=20) per row via iterative argmax ----------------
__global__ __launch_bounds__(256)
void topk_kernel(const float* __restrict__ dist, int* __restrict__ idx)
{
    __shared__ float vals[NN];
    __shared__ float rv[256];
    __shared__ int   ri[256];
    const int row = blockIdx.x;
    const int t = threadIdx.x;
    const float* dr = dist + (size_t)row * NN;
#pragma unroll
    for (int j = t; j < NN; j += 256) vals[j] = dr[j];
    __syncthreads();

    for (int kk = 0; kk < KNN; kk++) {
        float bv = -3.4e38f; int bi = NN;
        for (int j = t; j < NN; j += 256) {
            float v = vals[j];
            if (v > bv) { bv = v; bi = j; }     // strict >: keeps smallest index on tie
        }
        rv[t] = bv; ri[t] = bi;
        __syncthreads();
        for (int s = 128; s >= 32; s >>= 1) {
            if (t < s) {
                float v2 = rv[t + s]; int i2 = ri[t + s];
                if (v2 > rv[t] || (v2 == rv[t] && i2 < ri[t])) { rv[t] = v2; ri[t] = i2; }
            }
            __syncthreads();
        }
        if (t < 32) {
            float v = rv[t]; int bi2 = ri[t];
#pragma unroll
            for (int s = 16; s > 0; s >>= 1) {
                float v2 = __shfl_down_sync(0xffffffffu, v, s);
                int   i2 = __shfl_down_sync(0xffffffffu, bi2, s);
                if (v2 > v || (v2 == v && i2 < bi2)) { v = v2; bi2 = i2; }
            }
            if (t == 0) { idx[(size_t)row * KNN + kk] = bi2; vals[bi2] = -3.4e38f; }
        }
        __syncthreads();
    }
}

// ---------------- weight prep: Weff = Wc - Wn ----------------
__global__ void prep_weff_kernel(const float* __restrict__ w, float* __restrict__ weff,
                                 int C, int D) {
    int i = blockIdx.x * blockDim.x + threadIdx.x;
    if (i >= C * D) return;
    int d = i / C, c = i % C;
    weff[i] = w[(size_t)d * 2 * C + c] - w[(size_t)d * 2 * C + C + c];
}

// ---------------- zero small buffers ----------------
__global__ void zero_kernel(float* __restrict__ a, int n) {
    int i = blockIdx.x * blockDim.x + threadIdx.x;
    if (i < n) a[i] = 0.f;
}

// ---------------- gather h=U+V[idx]; per-(p,d) max/min over k; channel stats ----------------
__global__ void gather_kernel(const float* __restrict__ U, const float* __restrict__ V,
                              const int* __restrict__ idx,
                              float* __restrict__ maxh, float* __restrict__ minh,
                              float* __restrict__ stats, int D)
{
    const int p = blockIdx.x;
    const int d = threadIdx.x;
    __shared__ int sj[KNN];
    if (d < KNN) sj[d] = idx[(size_t)p * KNN + d];
    __syncthreads();
    const int b = p >> 11;                  // p / 2048
    const float* Vb = V + ((size_t)(b << 11)) * D;
    const float u = U[(size_t)p * D + d];
    float mx = -3.4e38f, mn = 3.4e38f, s = 0.f, s2 = 0.f;
#pragma unroll
    for (int kk = 0; kk < KNN; kk++) {
        float h = u + Vb[(size_t)sj[kk] * D + d];
        mx = fmaxf(mx, h); mn = fminf(mn, h);
        s += h; s2 = fmaf(h, h, s2);
    }
    maxh[(size_t)p * D + d] = mx;
    minh[(size_t)p * D + d] = mn;
    atomicAdd(&stats[d], s);
    atomicAdd(&stats[DMAX + d], s2);
}

// ---------------- BN finalize: per-channel scale/shift ----------------
__global__ void finalize_kernel(const float* __restrict__ stats,
                                const float* __restrict__ g, const float* __restrict__ be,
                                float* __restrict__ scale, float* __restrict__ shift,
                                float invcnt)
{
    int d = threadIdx.x;
    float mean = stats[d] * invcnt;
    float var  = stats[DMAX + d] * invcnt - mean * mean;
    float sc   = g[d] * rsqrtf(var + 1e-5f);
    scale[d] = sc;
    shift[d] = be[d] - mean * sc;
}

// ---------------- apply BN + ReLU + (already-max-pooled over k) ----------------
__global__ void apply_kernel(const float* __restrict__ maxh, const float* __restrict__ minh,
                             const float* __restrict__ scale, const float* __restrict__ shift,
                             float* __restrict__ out)
{
    size_t i = (size_t)blockIdx.x * blockDim.x + threadIdx.x;
    int d = threadIdx.x;
    float sc = scale[d];
    float h = (sc >= 0.f) ? maxh[i] : minh[i];
    out[i] = fmaxf(fmaf(h, sc, shift[d]), 0.f);
}

// ---------------- global max over N (values >= 0 after ReLU) ----------------
__global__ void gmax_kernel(const float* __restrict__ x3, float* __restrict__ gmax)
{
    const int b = blockIdx.x >> 6;        // 64 blocks per batch
    const int chunk = blockIdx.x & 63;
    const int d = threadIdx.x;            // 256
    float m = 0.f;
    const int n0 = chunk * 32;
#pragma unroll 4
    for (int n = n0; n < n0 + 32; n++)
        m = fmaxf(m, x3[((size_t)(b * NN + n)) * 256 + d]);
    atomicMax((int*)&gmax[b * 256 + d], __float_as_int(m));  // valid: m >= 0
}

// ---------------- final linear: out = gmax @ wo^T + bo ----------------
__global__ void final_linear_kernel(const float* __restrict__ gmax,
                                    const float* __restrict__ wo, const float* __restrict__ bo,
                                    float* __restrict__ out)
{
    const int b = blockIdx.x;
    const int o = threadIdx.x;            // 256
    __shared__ float h[256];
    h[o] = gmax[b * 256 + o];
    __syncthreads();
    float s = bo[o];
    const float* wr = wo + (size_t)o * 256;
#pragma unroll 8
    for (int c = 0; c < 256; c++) s = fmaf(h[c], wr[c], s);
    out[b * 256 + o] = s;
}

// ============================ host orchestration ============================
extern "C" void kernel_launch(void* const* d_in, const int* in_sizes, int n_in,
                              void* d_out, int out_size)
{
    (void)in_sizes; (void)n_in; (void)out_size;
    const float* x  = (const float*)d_in[0];
    const float* W [3] = {(const float*)d_in[1], (const float*)d_in[5],  (const float*)d_in[9]};
    const float* Bi[3] = {(const float*)d_in[2], (const float*)d_in[6],  (const float*)d_in[10]};
    const float* Ga[3] = {(const float*)d_in[3], (const float*)d_in[7],  (const float*)d_in[11]};
    const float* Be[3] = {(const float*)d_in[4], (const float*)d_in[8],  (const float*)d_in[12]};
    const float* wo = (const float*)d_in[13];
    const float* bo = (const float*)d_in[14];
    float* out = (float*)d_out;

    float *bufA, *bufB, *xx, *dist, *U, *V, *maxh, *minh, *weff, *stats, *scale, *shift, *gmax;
    int* idxp;
    cudaGetSymbolAddress((void**)&bufA,  g_bufA);
    cudaGetSymbolAddress((void**)&bufB,  g_bufB);
    cudaGetSymbolAddress((void**)&xx,    g_xx);
    cudaGetSymbolAddress((void**)&dist,  g_dist);
    cudaGetSymbolAddress((void**)&idxp,  g_idx);
    cudaGetSymbolAddress((void**)&U,     g_U);
    cudaGetSymbolAddress((void**)&V,     g_V);
    cudaGetSymbolAddress((void**)&maxh,  g_maxh);
    cudaGetSymbolAddress((void**)&minh,  g_minh);
    cudaGetSymbolAddress((void**)&weff,  g_weff);
    cudaGetSymbolAddress((void**)&stats, g_stats);
    cudaGetSymbolAddress((void**)&scale, g_scale);
    cudaGetSymbolAddress((void**)&shift, g_shift);
    cudaGetSymbolAddress((void**)&gmax,  g_gmax);

    const int Cs[3] = {3, 64, 128};
    const int Ds[3] = {64, 128, 256};
    const float* xin = x;
    float* outs[3] = {bufA, bufB, bufA};
    const dim3 blk(16, 16);

    for (int l = 0; l < 3; l++) {
        const int C = Cs[l], D = Ds[l];

        // squared norms
        xx_kernel<<<(NP + 255) / 256, 256>>>(xin, xx, C);

        // pairwise neg squared distances per batch: dist[b,i,j] = 2<xi,xj> - |xi|^2 - |xj|^2
        dim3 gd(NN / 64, NN / 64, BB);
        gemm_nt_kernel<<<gd, blk>>>(xin, C, (size_t)NN * C,
                                    xin, C, (size_t)NN * C,
                                    dist, NN, (size_t)NN * NN,
                                    NN, NN, C,
                                    1, nullptr, xx, xx, NN);

        // top-20 neighbor indices per point
        topk_kernel<<<NP, 256>>>(dist, idxp);

        // Weff = Wc - Wn
        prep_weff_kernel<<<(C * D + 255) / 256, 256>>>(W[l], weff, C, D);

        // U = X @ Weff^T + b ;  V = X @ Wn^T
        dim3 gu(D / 64, NP / 64, 1);
        gemm_nt_kernel<<<gu, blk>>>(xin, C, 0, weff, C, 0, U, D, 0,
                                    NP, D, C, 0, Bi[l], nullptr, nullptr, 0);
        gemm_nt_kernel<<<gu, blk>>>(xin, C, 0, W[l] + C, 2 * C, 0, V, D, 0,
                                    NP, D, C, 0, nullptr, nullptr, nullptr, 0);

        // stats reset, gather + per-point max/min + channel sums
        zero_kernel<<<2, 256>>>(stats, 2 * DMAX);
        gather_kernel<<<NP, D>>>(U, V, idxp, maxh, minh, stats, D);

        // BN scale/shift, then apply BN+ReLU to the k-pooled extremum
        finalize_kernel<<<1, D>>>(stats, Ga[l], Be[l], scale, shift,
                                  1.f / (float)((size_t)NP * KNN));
        apply_kernel<<<NP, D>>>(maxh, minh, scale, shift, outs[l]);

        xin = outs[l];
    }

    // global max over N, then final linear
    zero_kernel<<<8, 256>>>(gmax, BB * DMAX);
    gmax_kernel<<<BB * 64, 256>>>(xin, gmax);
    final_linear_kernel<<<BB, 256>>>(gmax, wo, bo, out);
}

// round 7
// speedup vs baseline: 1.0024x; 1.0004x over previous
#include <cuda_runtime.h>
#include <math.h>
#include <stdint.h>

#define BB   8
#define NN   2048
#define NP   (BB*NN)      /* 16384 points total */
#define KNN  20
#define DMAX 256

// ---------------- device scratch (no allocations allowed) ----------------
__device__ float g_bufA[(size_t)NP * DMAX];
__device__ float g_bufB[(size_t)NP * DMAX];
__device__ float g_xx[NP];
__device__ float g_dist[(size_t)BB * NN * NN];      // 134 MB
__device__ int   g_idx[(size_t)NP * KNN];
__device__ float g_U[(size_t)NP * DMAX];
__device__ float g_V[(size_t)NP * DMAX];
__device__ float g_maxh[(size_t)NP * DMAX];
__device__ float g_minh[(size_t)NP * DMAX];
__device__ float g_weff[DMAX * 128];                // (Wc - Wn), D x C (C <= 128)
__device__ float g_stats[2 * DMAX];                 // [0..255]=sum, [256..511]=sumsq
__device__ float g_scale[DMAX];
__device__ float g_shift[DMAX];
__device__ float g_gmax[BB * DMAX];

// ---------------- squared norms ----------------
__global__ void xx_kernel(const float* __restrict__ x, float* __restrict__ xx, int C) {
    int p = blockIdx.x * blockDim.x + threadIdx.x;
    if (p >= NP) return;
    const float* xr = x + (size_t)p * C;
    float s = 0.f;
    for (int c = 0; c < C; c++) s = fmaf(xr[c], xr[c], s);
    xx[p] = s;
}

// ---------------- generic tiled NT GEMM: out[i,j] = dot(A[i,:], B[j,:]) ----------------
// epi==0: out = acc + (bias ? bias[j] : 0)
// epi==1: out = 2*acc - xxA[i] - xxB[j]   (neg squared distance for kNN)
__global__ __launch_bounds__(256)
void gemm_nt_kernel(const float* __restrict__ A, int lda, size_t strideA,
                    const float* __restrict__ Bm, int ldb, size_t strideB,
                    float* __restrict__ Cm, int ldc, size_t strideC,
                    int M, int Ncols, int Kd,
                    int epi, const float* __restrict__ bias,
                    const float* __restrict__ xxA, const float* __restrict__ xxB,
                    int xxStride)
{
    __shared__ float As[16][68];
    __shared__ float Bs[16][68];
    const int bx = blockIdx.x, by = blockIdx.y, bz = blockIdx.z;
    const float* Ab = A  + (size_t)bz * strideA;
    const float* Bb = Bm + (size_t)bz * strideB;
    float*       Cb = Cm + (size_t)bz * strideC;
    const int tx = threadIdx.x, ty = threadIdx.y;
    const int tid = ty * 16 + tx;
    const int row0 = by * 64, col0 = bx * 64;

    float acc[4][4];
#pragma unroll
    for (int i = 0; i < 4; i++)
#pragma unroll
        for (int j = 0; j < 4; j++) acc[i][j] = 0.f;

    for (int k0 = 0; k0 < Kd; k0 += 16) {
#pragma unroll
        for (int l = 0; l < 4; l++) {
            int e  = tid + l * 256;   // 0..1023
            int r  = e >> 4;
            int kk = e & 15;
            float va = 0.f, vb = 0.f;
            if (k0 + kk < Kd) {
                va = Ab[(size_t)(row0 + r) * lda + k0 + kk];
                vb = Bb[(size_t)(col0 + r) * ldb + k0 + kk];
            }
            As[kk][r] = va;
            Bs[kk][r] = vb;
        }
        __syncthreads();
#pragma unroll
        for (int kk = 0; kk < 16; kk++) {
            float a[4], b[4];
#pragma unroll
            for (int i = 0; i < 4; i++) a[i] = As[kk][ty * 4 + i];
#pragma unroll
            for (int j = 0; j < 4; j++) b[j] = Bs[kk][tx * 4 + j];
#pragma unroll
            for (int i = 0; i < 4; i++)
#pragma unroll
                for (int j = 0; j < 4; j++) acc[i][j] = fmaf(a[i], b[j], acc[i][j]);
        }
        __syncthreads();
    }

#pragma unroll
    for (int i = 0; i < 4; i++) {
        int r = row0 + ty * 4 + i;
#pragma unroll
        for (int j = 0; j < 4; j++) {
            int c = col0 + tx * 4 + j;
            float v;
            if (epi == 0) {
                v = acc[i][j] + (bias ? bias[c] : 0.f);
            } else {
                v = 2.f * acc[i][j] - xxA[(size_t)bz * xxStride + r]
                                    - xxB[(size_t)bz * xxStride + c];
            }
            Cb[(size_t)r * ldc + c] = v;
        }
    }
}

// ---------------- top-k (k=20) per row via iterative argmax ----------------
__global__ __launch_bounds__(256)
void topk_kernel(const float* __restrict__ dist, int* __restrict__ idx)
{
    __shared__ float vals[NN];
    __shared__ float rv[256];
    __shared__ int   ri[256];
    const int row = blockIdx.x;
    const int t = threadIdx.x;
    const float* dr = dist + (size_t)row * NN;
#pragma unroll
    for (int j = t; j < NN; j += 256) vals[j] = dr[j];
    __syncthreads();

    for (int kk = 0; kk < KNN; kk++) {
        float bv = -3.4e38f; int bi = NN;
        for (int j = t; j < NN; j += 256) {
            float v = vals[j];
            if (v > bv) { bv = v; bi = j; }     // strict >: keeps smallest index on tie
        }
        rv[t] = bv; ri[t] = bi;
        __syncthreads();
        for (int s = 128; s >= 32; s >>= 1) {
            if (t < s) {
                float v2 = rv[t + s]; int i2 = ri[t + s];
                if (v2 > rv[t] || (v2 == rv[t] && i2 < ri[t])) { rv[t] = v2; ri[t] = i2; }
            }
            __syncthreads();
        }
        if (t < 32) {
            float v = rv[t]; int bi2 = ri[t];
#pragma unroll
            for (int s = 16; s > 0; s >>= 1) {
                float v2 = __shfl_down_sync(0xffffffffu, v, s);
                int   i2 = __shfl_down_sync(0xffffffffu, bi2, s);
                if (v2 > v || (v2 == v && i2 < bi2)) { v = v2; bi2 = i2; }
            }
            if (t == 0) { idx[(size_t)row * KNN + kk] = bi2; vals[bi2] = -3.4e38f; }
        }
        __syncthreads();
    }
}

// ---------------- weight prep: Weff = Wc - Wn ----------------
__global__ void prep_weff_kernel(const float* __restrict__ w, float* __restrict__ weff,
                                 int C, int D) {
    int i = blockIdx.x * blockDim.x + threadIdx.x;
    if (i >= C * D) return;
    int d = i / C, c = i % C;
    weff[i] = w[(size_t)d * 2 * C + c] - w[(size_t)d * 2 * C + C + c];
}

// ---------------- zero small buffers ----------------
__global__ void zero_kernel(float* __restrict__ a, int n) {
    int i = blockIdx.x * blockDim.x + threadIdx.x;
    if (i < n) a[i] = 0.f;
}

// ---------------- gather h=U+V[idx]; per-(p,d) max/min over k; channel stats ----------------
__global__ void gather_kernel(const float* __restrict__ U, const float* __restrict__ V,
                              const int* __restrict__ idx,
                              float* __restrict__ maxh, float* __restrict__ minh,
                              float* __restrict__ stats, int D)
{
    const int p = blockIdx.x;
    const int d = threadIdx.x;
    __shared__ int sj[KNN];
    if (d < KNN) sj[d] = idx[(size_t)p * KNN + d];
    __syncthreads();
    const int b = p >> 11;                  // p / 2048
    const float* Vb = V + ((size_t)(b << 11)) * D;
    const float u = U[(size_t)p * D + d];
    float mx = -3.4e38f, mn = 3.4e38f, s = 0.f, s2 = 0.f;
#pragma unroll
    for (int kk = 0; kk < KNN; kk++) {
        float h = u + Vb[(size_t)sj[kk] * D + d];
        mx = fmaxf(mx, h); mn = fminf(mn, h);
        s += h; s2 = fmaf(h, h, s2);
    }
    maxh[(size_t)p * D + d] = mx;
    minh[(size_t)p * D + d] = mn;
    atomicAdd(&stats[d], s);
    atomicAdd(&stats[DMAX + d], s2);
}

// ---------------- BN finalize: per-channel scale/shift ----------------
__global__ void finalize_kernel(const float* __restrict__ stats,
                                const float* __restrict__ g, const float* __restrict__ be,
                                float* __restrict__ scale, float* __restrict__ shift,
                                float invcnt)
{
    int d = threadIdx.x;
    float mean = stats[d] * invcnt;
    float var  = stats[DMAX + d] * invcnt - mean * mean;
    float sc   = g[d] * rsqrtf(var + 1e-5f);
    scale[d] = sc;
    shift[d] = be[d] - mean * sc;
}

// ---------------- apply BN + ReLU + (already-max-pooled over k) ----------------
__global__ void apply_kernel(const float* __restrict__ maxh, const float* __restrict__ minh,
                             const float* __restrict__ scale, const float* __restrict__ shift,
                             float* __restrict__ out)
{
    size_t i = (size_t)blockIdx.x * blockDim.x + threadIdx.x;
    int d = threadIdx.x;
    float sc = scale[d];
    float h = (sc >= 0.f) ? maxh[i] : minh[i];
    out[i] = fmaxf(fmaf(h, sc, shift[d]), 0.f);
}

// ---------------- global max over N (values >= 0 after ReLU) ----------------
__global__ void gmax_kernel(const float* __restrict__ x3, float* __restrict__ gmax)
{
    const int b = blockIdx.x >> 6;        // 64 blocks per batch
    const int chunk = blockIdx.x & 63;
    const int d = threadIdx.x;            // 256
    float m = 0.f;
    const int n0 = chunk * 32;
#pragma unroll 4
    for (int n = n0; n < n0 + 32; n++)
        m = fmaxf(m, x3[((size_t)(b * NN + n)) * 256 + d]);
    atomicMax((int*)&gmax[b * 256 + d], __float_as_int(m));  // valid: m >= 0
}

// ---------------- final linear: out = gmax @ wo^T + bo ----------------
__global__ void final_linear_kernel(const float* __restrict__ gmax,
                                    const float* __restrict__ wo, const float* __restrict__ bo,
                                    float* __restrict__ out)
{
    const int b = blockIdx.x;
    const int o = threadIdx.x;            // 256
    __shared__ float h[256];
    h[o] = gmax[b * 256 + o];
    __syncthreads();
    float s = bo[o];
    const float* wr = wo + (size_t)o * 256;
#pragma unroll 8
    for (int c = 0; c < 256; c++) s = fmaf(h[c], wr[c], s);
    out[b * 256 + o] = s;
}

// ============================ host orchestration ============================
extern "C" void kernel_launch(void* const* d_in, const int* in_sizes, int n_in,
                              void* d_out, int out_size)
{
    (void)in_sizes; (void)n_in; (void)out_size;
    const float* x  = (const float*)d_in[0];
    const float* W [3] = {(const float*)d_in[1], (const float*)d_in[5],  (const float*)d_in[9]};
    const float* Bi[3] = {(const float*)d_in[2], (const float*)d_in[6],  (const float*)d_in[10]};
    const float* Ga[3] = {(const float*)d_in[3], (const float*)d_in[7],  (const float*)d_in[11]};
    const float* Be[3] = {(const float*)d_in[4], (const float*)d_in[8],  (const float*)d_in[12]};
    const float* wo = (const float*)d_in[13];
    const float* bo = (const float*)d_in[14];
    float* out = (float*)d_out;

    float *bufA, *bufB, *xx, *dist, *U, *V, *maxh, *minh, *weff, *stats, *scale, *shift, *gmax;
    int* idxp;
    cudaGetSymbolAddress((void**)&bufA,  g_bufA);
    cudaGetSymbolAddress((void**)&bufB,  g_bufB);
    cudaGetSymbolAddress((void**)&xx,    g_xx);
    cudaGetSymbolAddress((void**)&dist,  g_dist);
    cudaGetSymbolAddress((void**)&idxp,  g_idx);
    cudaGetSymbolAddress((void**)&U,     g_U);
    cudaGetSymbolAddress((void**)&V,     g_V);
    cudaGetSymbolAddress((void**)&maxh,  g_maxh);
    cudaGetSymbolAddress((void**)&minh,  g_minh);
    cudaGetSymbolAddress((void**)&weff,  g_weff);
    cudaGetSymbolAddress((void**)&stats, g_stats);
    cudaGetSymbolAddress((void**)&scale, g_scale);
    cudaGetSymbolAddress((void**)&shift, g_shift);
    cudaGetSymbolAddress((void**)&gmax,  g_gmax);

    const int Cs[3] = {3, 64, 128};
    const int Ds[3] = {64, 128, 256};
    const float* xin = x;
    float* outs[3] = {bufA, bufB, bufA};
    const dim3 blk(16, 16);

    for (int l = 0; l < 3; l++) {
        const int C = Cs[l], D = Ds[l];

        // squared norms
        xx_kernel<<<(NP + 255) / 256, 256>>>(xin, xx, C);

        // pairwise neg squared distances per batch: dist[b,i,j] = 2<xi,xj> - |xi|^2 - |xj|^2
        dim3 gd(NN / 64, NN / 64, BB);
        gemm_nt_kernel<<<gd, blk>>>(xin, C, (size_t)NN * C,
                                    xin, C, (size_t)NN * C,
                                    dist, NN, (size_t)NN * NN,
                                    NN, NN, C,
                                    1, nullptr, xx, xx, NN);

        // top-20 neighbor indices per point
        topk_kernel<<<NP, 256>>>(dist, idxp);

        // Weff = Wc - Wn
        prep_weff_kernel<<<(C * D + 255) / 256, 256>>>(W[l], weff, C, D);

        // U = X @ Weff^T + b ;  V = X @ Wn^T
        dim3 gu(D / 64, NP / 64, 1);
        gemm_nt_kernel<<<gu, blk>>>(xin, C, 0, weff, C, 0, U, D, 0,
                                    NP, D, C, 0, Bi[l], nullptr, nullptr, 0);
        gemm_nt_kernel<<<gu, blk>>>(xin, C, 0, W[l] + C, 2 * C, 0, V, D, 0,
                                    NP, D, C, 0, nullptr, nullptr, nullptr, 0);

        // stats reset, gather + per-point max/min + channel sums
        zero_kernel<<<2, 256>>>(stats, 2 * DMAX);
        gather_kernel<<<NP, D>>>(U, V, idxp, maxh, minh, stats, D);

        // BN scale/shift, then apply BN+ReLU to the k-pooled extremum
        finalize_kernel<<<1, D>>>(stats, Ga[l], Be[l], scale, shift,
                                  1.f / (float)((size_t)NP * KNN));
        apply_kernel<<<NP, D>>>(maxh, minh, scale, shift, outs[l]);

        xin = outs[l];
    }

    // global max over N, then final linear
    zero_kernel<<<8, 256>>>(gmax, BB * DMAX);
    gmax_kernel<<<BB * 64, 256>>>(xin, gmax);
    final_linear_kernel<<<BB, 256>>>(gmax, wo, bo, out);
}